// round 14
// baseline (speedup 1.0000x reference)
#include <cuda_runtime.h>
#include <cstdint>

typedef unsigned long long ull;

#define BATCH 8192
#define SEQT  256
#define HID   32
#define RPW   3
#define ENC_CTAS ((BATCH + RPW - 1) / RPW)   // 2731

// scratch: decoder per-row gate preactivations, transposed for coalesced loads
__device__ float g_pre[4][BATCH];

// ---- f32x2 helpers ----
__device__ __forceinline__ void unpackf2(ull v, float &a, float &b) {
    unsigned lo, hi;
    asm("mov.b64 {%0, %1}, %2;" : "=r"(lo), "=r"(hi) : "l"(v));
    a = __uint_as_float(lo); b = __uint_as_float(hi);
}

// ---- bf16x2 helpers ----
__device__ __forceinline__ void hfma2(unsigned &acc, unsigned a, unsigned b) {
    asm("fma.rn.bf16x2 %0, %1, %2, %0;" : "+r"(acc) : "r"(a), "r"(b));
}
__device__ __forceinline__ unsigned bfpack(float hi, float lo) {
    unsigned r;
    asm("cvt.rn.bf16x2.f32 %0, %1, %2;" : "=r"(r) : "f"(hi), "f"(lo));
    return r;
}
// horizontal sum of a bf16x2 accumulator in f32 (bf16->f32 is an exact shift)
__device__ __forceinline__ float bfsum(unsigned v) {
    return __uint_as_float(v << 16) + __uint_as_float(v & 0xffff0000u);
}

// ---- activations: all MUFU.TANH (calibrated error transfer) ----
__device__ __forceinline__ float tanha(float x) {
    float y;
    asm("tanh.approx.f32 %0, %1;" : "=f"(y) : "f"(x));
    return y;
}
__device__ __forceinline__ float sigm_pre(float acc_half_x) {   // sig(2x) of acc
    return fmaf(0.5f, tanha(acc_half_x), 0.5f);
}

// ============================================================================
// Encoder: ONE WARP per CTA, THREE rows per warp. All recurrent weights in
// bf16x2 (64 regs/lane, shared across rows); i/f/o pre-scaled by 0.5 for the
// sigmoid fold; g accumulated in two bf16x2 registers (halved rounding walk),
// summed exactly in f32. x-term + bias exact f32, added after the dot.
// Single bf16 h ping-pong buffer per row. ~120 regs -> 16 warps/SM,
// 48 independent recurrence chains per SM.
// ============================================================================
__global__ void __launch_bounds__(32, 16) enc_kernel(
    const float* __restrict__ x,      // [B, T]
    const float* __restrict__ eWih,   // [128]
    const float* __restrict__ eWhh,   // [128, 32]
    const float* __restrict__ eBih,   // [128]
    const float* __restrict__ eBhh,   // [128]
    const float* __restrict__ dWih,   // [4, 32]
    const float* __restrict__ dBih,   // [4]
    const float* __restrict__ dBhh)   // [4]
{
    __shared__ float xs[RPW][SEQT];
    __shared__ __align__(16) unsigned short hb[2][RPW][HID];  // bf16 h ping-pong

    const int lane  = threadIdx.x;
    const int rbase = blockIdx.x * RPW;

    int rows[RPW];
    #pragma unroll
    for (int r = 0; r < RPW; ++r)
        rows[r] = min(rbase + r, BATCH - 1);   // last CTA duplicates row 8191

    // stage x rows (float4-coalesced)
    #pragma unroll
    for (int r = 0; r < RPW; ++r) {
        const float4* s4 = (const float4*)(x + (size_t)rows[r] * SEQT);
        ((float4*)xs[r])[lane]      = s4[lane];
        ((float4*)xs[r])[32 + lane] = s4[32 + lane];
    }

    // ---- per-lane weights, all bf16x2 over k-pairs (shared by all rows) ----
    unsigned wI[16], wF[16], wG[16], wO[16];
    {
        const ull* ri = (const ull*)(eWhh + (size_t)(      lane) * HID);
        const ull* rf = (const ull*)(eWhh + (size_t)(32  + lane) * HID);
        const ull* rg = (const ull*)(eWhh + (size_t)(64  + lane) * HID);
        const ull* ro = (const ull*)(eWhh + (size_t)(96  + lane) * HID);
        #pragma unroll
        for (int k = 0; k < 16; ++k) {
            float lo, hi;
            unpackf2(ri[k], lo, hi);  wI[k] = bfpack(0.5f * hi, 0.5f * lo);
            unpackf2(rf[k], lo, hi);  wF[k] = bfpack(0.5f * hi, 0.5f * lo);
            unpackf2(rg[k], lo, hi);  wG[k] = bfpack(hi, lo);
            unpackf2(ro[k], lo, hi);  wO[k] = bfpack(0.5f * hi, 0.5f * lo);
        }
    }
    const float bi = 0.5f * (eBih[lane]      + eBhh[lane]);
    const float bf = 0.5f * (eBih[32 + lane] + eBhh[32 + lane]);
    const float bg =        (eBih[64 + lane] + eBhh[64 + lane]);
    const float bo = 0.5f * (eBih[96 + lane] + eBhh[96 + lane]);
    const float vi = 0.5f * eWih[lane];
    const float vf = 0.5f * eWih[32 + lane];
    const float vg =        eWih[64 + lane];
    const float vo = 0.5f * eWih[96 + lane];

    #pragma unroll
    for (int r = 0; r < RPW; ++r)
        hb[0][r][lane] = 0;   // bf16 +0.0
    __syncwarp();

    float h[RPW], c[RPW];
    #pragma unroll
    for (int r = 0; r < RPW; ++r) { h[r] = 0.0f; c[r] = 0.0f; }

    #pragma unroll 1
    for (int t = 0; t < SEQT; t += 2) {
        #pragma unroll
        for (int p = 0; p < 2; ++p) {
            unsigned ai[RPW], af[RPW], ao[RPW], ag0[RPW], ag1[RPW];
            float    ini[RPW], inf_[RPW], ing[RPW], ino[RPW];

            #pragma unroll
            for (int r = 0; r < RPW; ++r) {
                const float xv = xs[r][t + p];
                ini[r]  = fmaf(xv, vi, bi);
                inf_[r] = fmaf(xv, vf, bf);
                ing[r]  = fmaf(xv, vg, bg);
                ino[r]  = fmaf(xv, vo, bo);
                ai[r] = 0; af[r] = 0; ao[r] = 0; ag0[r] = 0; ag1[r] = 0;
            }

            #pragma unroll
            for (int q = 0; q < 4; ++q) {
                #pragma unroll
                for (int r = 0; r < RPW; ++r) {
                    const uint4 hv = ((const uint4*)hb[p][r])[q]; // LDS.128
                    hfma2(ai[r],  wI[4 * q + 0], hv.x);
                    hfma2(af[r],  wF[4 * q + 0], hv.x);
                    hfma2(ag0[r], wG[4 * q + 0], hv.x);
                    hfma2(ao[r],  wO[4 * q + 0], hv.x);
                    hfma2(ai[r],  wI[4 * q + 1], hv.y);
                    hfma2(af[r],  wF[4 * q + 1], hv.y);
                    hfma2(ag1[r], wG[4 * q + 1], hv.y);
                    hfma2(ao[r],  wO[4 * q + 1], hv.y);
                    hfma2(ai[r],  wI[4 * q + 2], hv.z);
                    hfma2(af[r],  wF[4 * q + 2], hv.z);
                    hfma2(ag0[r], wG[4 * q + 2], hv.z);
                    hfma2(ao[r],  wO[4 * q + 2], hv.z);
                    hfma2(ai[r],  wI[4 * q + 3], hv.w);
                    hfma2(af[r],  wF[4 * q + 3], hv.w);
                    hfma2(ag1[r], wG[4 * q + 3], hv.w);
                    hfma2(ao[r],  wO[4 * q + 3], hv.w);
                }
            }

            #pragma unroll
            for (int r = 0; r < RPW; ++r) {
                const float I = sigm_pre(bfsum(ai[r]) + ini[r]);
                const float F = sigm_pre(bfsum(af[r]) + inf_[r]);
                const float G = tanha((bfsum(ag0[r]) + bfsum(ag1[r])) + ing[r]);
                const float O = sigm_pre(bfsum(ao[r]) + ino[r]);
                c[r] = fmaf(F, c[r], I * G);
                h[r] = O * tanha(c[r]);
                unsigned short h16;
                asm("cvt.rn.bf16.f32 %0, %1;" : "=h"(h16) : "f"(h[r]));
                hb[p ^ 1][r][lane] = h16;
            }
            __syncwarp();
        }
    }

    // decoder input projection per row: pg = sum_j dWih[g][j]*h[j]
    const float dw0 = dWih[lane];
    const float dw1 = dWih[32 + lane];
    const float dw2 = dWih[64 + lane];
    const float dw3 = dWih[96 + lane];
    #pragma unroll
    for (int r = 0; r < RPW; ++r) {
        float p0 = h[r] * dw0;
        float p1 = h[r] * dw1;
        float p2 = h[r] * dw2;
        float p3 = h[r] * dw3;
        #pragma unroll
        for (int m = 16; m > 0; m >>= 1) {
            p0 += __shfl_xor_sync(0xffffffffu, p0, m);
            p1 += __shfl_xor_sync(0xffffffffu, p1, m);
            p2 += __shfl_xor_sync(0xffffffffu, p2, m);
            p3 += __shfl_xor_sync(0xffffffffu, p3, m);
        }
        if (lane == 0) {
            g_pre[0][rows[r]] = p0 + dBih[0] + dBhh[0];
            g_pre[1][rows[r]] = p1 + dBih[1] + dBhh[1];
            g_pre[2][rows[r]] = p2 + dBih[2] + dBhh[2];
            g_pre[3][rows[r]] = p3 + dBih[3] + dBhh[3];
        }
    }
}

// ============================================================================
// Decoder: one batch row per THREAD (H=1 scalar recurrence). 8192 threads.
// ============================================================================
__global__ void __launch_bounds__(32) dec_kernel(
    const float* __restrict__ dWhh,   // [4]
    float* __restrict__ out)          // [B, T]
{
    const int r = blockIdx.x * 32 + threadIdx.x;

    const float pre0 = 0.5f * g_pre[0][r];
    const float pre1 = 0.5f * g_pre[1][r];
    const float pre2 =        g_pre[2][r];
    const float pre3 = 0.5f * g_pre[3][r];
    const float q0 = 0.5f * dWhh[0];
    const float q1 = 0.5f * dWhh[1];
    const float q2 =        dWhh[2];
    const float q3 = 0.5f * dWhh[3];

    float hd = 0.0f, cd = 0.0f;
    float* orow = out + (size_t)r * SEQT;

    #pragma unroll 1
    for (int t = 0; t < SEQT; t += 4) {
        float v[4];
        #pragma unroll
        for (int s = 0; s < 4; ++s) {
            const float I = sigm_pre(fmaf(hd, q0, pre0));
            const float F = sigm_pre(fmaf(hd, q1, pre1));
            const float G = tanha(fmaf(hd, q2, pre2));
            const float O = sigm_pre(fmaf(hd, q3, pre3));
            cd = fmaf(F, cd, I * G);
            hd = O * tanha(cd);
            v[s] = hd;
        }
        *(float4*)(orow + t) = make_float4(v[0], v[1], v[2], v[3]);
    }
}

extern "C" void kernel_launch(void* const* d_in, const int* in_sizes, int n_in,
                              void* d_out, int out_size) {
    (void)in_sizes; (void)n_in; (void)out_size;
    enc_kernel<<<ENC_CTAS, 32>>>(
        (const float*)d_in[0],
        (const float*)d_in[1], (const float*)d_in[2],
        (const float*)d_in[3], (const float*)d_in[4],
        (const float*)d_in[5],
        (const float*)d_in[7], (const float*)d_in[8]);
    dec_kernel<<<BATCH / 32, 32>>>(
        (const float*)d_in[6],
        (float*)d_out);
}

// round 15
// speedup vs baseline: 1.0214x; 1.0214x over previous
#include <cuda_runtime.h>
#include <cstdint>

typedef unsigned long long ull;

#define BATCH 8192
#define SEQT  256
#define HID   32

// scratch: decoder per-row gate preactivations, transposed for coalesced loads
__device__ float g_pre[4][BATCH];

// ---- f32x2 helpers ----
__device__ __forceinline__ void unpackf2(ull v, float &a, float &b) {
    unsigned lo, hi;
    asm("mov.b64 {%0, %1}, %2;" : "=r"(lo), "=r"(hi) : "l"(v));
    a = __uint_as_float(lo); b = __uint_as_float(hi);
}

// ---- bf16x2 helpers ----
__device__ __forceinline__ void hfma2(unsigned &acc, unsigned a, unsigned b) {
    asm("fma.rn.bf16x2 %0, %1, %2, %0;" : "+r"(acc) : "r"(a), "r"(b));
}
__device__ __forceinline__ unsigned bfpack(float hi, float lo) {
    unsigned r;
    asm("cvt.rn.bf16x2.f32 %0, %1, %2;" : "=r"(r) : "f"(hi), "f"(lo));
    return r;
}
// horizontal sum of a bf16x2 accumulator in f32 (bf16->f32 is an exact shift)
__device__ __forceinline__ float bfsum(unsigned v) {
    return __uint_as_float(v << 16) + __uint_as_float(v & 0xffff0000u);
}

// ---- activations: all MUFU.TANH (calibrated error transfer) ----
__device__ __forceinline__ float tanha(float x) {
    float y;
    asm("tanh.approx.f32 %0, %1;" : "=f"(y) : "f"(x));
    return y;
}
__device__ __forceinline__ float sigm_pre(float acc_half_x) {   // sig(2x) of acc
    return fmaf(0.5f, tanha(acc_half_x), 0.5f);
}

// ============================================================================
// Encoder: ONE WARP per CTA, TWO rows per warp (flat registers — the proven
// fixed point). All recurrent weights in bf16x2 (i/f/o pre-scaled by 0.5 for
// the sigmoid fold; g accumulated in two bf16x2 registers, summed exactly in
// f32). x-term + bias exact f32, added after the dot. Single bf16 h
// ping-pong buffer. 18 warps/SM target (reg cap 113).
// ============================================================================
__global__ void __launch_bounds__(32, 18) enc_kernel(
    const float* __restrict__ x,      // [B, T]
    const float* __restrict__ eWih,   // [128]
    const float* __restrict__ eWhh,   // [128, 32]
    const float* __restrict__ eBih,   // [128]
    const float* __restrict__ eBhh,   // [128]
    const float* __restrict__ dWih,   // [4, 32]
    const float* __restrict__ dBih,   // [4]
    const float* __restrict__ dBhh)   // [4]
{
    __shared__ float xsA[SEQT], xsB[SEQT];
    __shared__ __align__(16) unsigned short hbA[2][HID], hbB[2][HID];  // bf16 h

    const int lane = threadIdx.x;
    const int rA   = blockIdx.x * 2;
    const int rB   = rA + 1;

    // stage both x rows (float4-coalesced)
    {
        const float4* a4 = (const float4*)(x + (size_t)rA * SEQT);
        const float4* b4 = (const float4*)(x + (size_t)rB * SEQT);
        ((float4*)xsA)[lane]      = a4[lane];
        ((float4*)xsA)[32 + lane] = a4[32 + lane];
        ((float4*)xsB)[lane]      = b4[lane];
        ((float4*)xsB)[32 + lane] = b4[32 + lane];
    }

    // ---- per-lane weights, all bf16x2 over k-pairs ----
    unsigned wI[16], wF[16], wG[16], wO[16];
    {
        const ull* ri = (const ull*)(eWhh + (size_t)(      lane) * HID);
        const ull* rf = (const ull*)(eWhh + (size_t)(32  + lane) * HID);
        const ull* rg = (const ull*)(eWhh + (size_t)(64  + lane) * HID);
        const ull* ro = (const ull*)(eWhh + (size_t)(96  + lane) * HID);
        #pragma unroll
        for (int k = 0; k < 16; ++k) {
            float lo, hi;
            unpackf2(ri[k], lo, hi);  wI[k] = bfpack(0.5f * hi, 0.5f * lo);
            unpackf2(rf[k], lo, hi);  wF[k] = bfpack(0.5f * hi, 0.5f * lo);
            unpackf2(rg[k], lo, hi);  wG[k] = bfpack(hi, lo);
            unpackf2(ro[k], lo, hi);  wO[k] = bfpack(0.5f * hi, 0.5f * lo);
        }
    }
    const float bi = 0.5f * (eBih[lane]      + eBhh[lane]);
    const float bf = 0.5f * (eBih[32 + lane] + eBhh[32 + lane]);
    const float bg =        (eBih[64 + lane] + eBhh[64 + lane]);
    const float bo = 0.5f * (eBih[96 + lane] + eBhh[96 + lane]);
    const float vi = 0.5f * eWih[lane];
    const float vf = 0.5f * eWih[32 + lane];
    const float vg =        eWih[64 + lane];
    const float vo = 0.5f * eWih[96 + lane];

    hbA[0][lane] = 0;     // bf16 +0.0
    hbB[0][lane] = 0;
    __syncwarp();

    float hA = 0.0f, cA = 0.0f;
    float hB = 0.0f, cB = 0.0f;

    #pragma unroll 1
    for (int t = 0; t < SEQT; t += 2) {
        #pragma unroll
        for (int p = 0; p < 2; ++p) {
            const uint4* bhA = (const uint4*)hbA[p];
            const uint4* bhB = (const uint4*)hbB[p];
            const float xa = xsA[t + p];
            const float xb = xsB[t + p];

            // f32 init terms (exact; added after the dots)
            const float iniA = fmaf(xa, vi, bi), infA = fmaf(xa, vf, bf);
            const float ingA = fmaf(xa, vg, bg), inoA = fmaf(xa, vo, bo);
            const float iniB = fmaf(xb, vi, bi), infB = fmaf(xb, vf, bf);
            const float ingB = fmaf(xb, vg, bg), inoB = fmaf(xb, vo, bo);

            // bf16x2 accumulators; g split over two to halve rounding walk
            unsigned aiA = 0, afA = 0, aoA = 0, ag0A = 0, ag1A = 0;
            unsigned aiB = 0, afB = 0, aoB = 0, ag0B = 0, ag1B = 0;

            #pragma unroll
            for (int q = 0; q < 4; ++q) {
                const uint4 ha = bhA[q];         // LDS.128: 8 bf16 h values
                const uint4 hb = bhB[q];
                hfma2(aiA,  wI[4 * q + 0], ha.x);  hfma2(aiB,  wI[4 * q + 0], hb.x);
                hfma2(afA,  wF[4 * q + 0], ha.x);  hfma2(afB,  wF[4 * q + 0], hb.x);
                hfma2(ag0A, wG[4 * q + 0], ha.x);  hfma2(ag0B, wG[4 * q + 0], hb.x);
                hfma2(aoA,  wO[4 * q + 0], ha.x);  hfma2(aoB,  wO[4 * q + 0], hb.x);
                hfma2(aiA,  wI[4 * q + 1], ha.y);  hfma2(aiB,  wI[4 * q + 1], hb.y);
                hfma2(afA,  wF[4 * q + 1], ha.y);  hfma2(afB,  wF[4 * q + 1], hb.y);
                hfma2(ag1A, wG[4 * q + 1], ha.y);  hfma2(ag1B, wG[4 * q + 1], hb.y);
                hfma2(aoA,  wO[4 * q + 1], ha.y);  hfma2(aoB,  wO[4 * q + 1], hb.y);
                hfma2(aiA,  wI[4 * q + 2], ha.z);  hfma2(aiB,  wI[4 * q + 2], hb.z);
                hfma2(afA,  wF[4 * q + 2], ha.z);  hfma2(afB,  wF[4 * q + 2], hb.z);
                hfma2(ag0A, wG[4 * q + 2], ha.z);  hfma2(ag0B, wG[4 * q + 2], hb.z);
                hfma2(aoA,  wO[4 * q + 2], ha.z);  hfma2(aoB,  wO[4 * q + 2], hb.z);
                hfma2(aiA,  wI[4 * q + 3], ha.w);  hfma2(aiB,  wI[4 * q + 3], hb.w);
                hfma2(afA,  wF[4 * q + 3], ha.w);  hfma2(afB,  wF[4 * q + 3], hb.w);
                hfma2(ag1A, wG[4 * q + 3], ha.w);  hfma2(ag1B, wG[4 * q + 3], hb.w);
                hfma2(aoA,  wO[4 * q + 3], ha.w);  hfma2(aoB,  wO[4 * q + 3], hb.w);
            }

            // ---- activations + state update (all MUFU.TANH) ----
            const float IA = sigm_pre(bfsum(aiA) + iniA);
            const float IB = sigm_pre(bfsum(aiB) + iniB);
            const float FA = sigm_pre(bfsum(afA) + infA);
            const float FB = sigm_pre(bfsum(afB) + infB);
            const float GA = tanha((bfsum(ag0A) + bfsum(ag1A)) + ingA);
            const float GB = tanha((bfsum(ag0B) + bfsum(ag1B)) + ingB);
            const float OA = sigm_pre(bfsum(aoA) + inoA);
            const float OB = sigm_pre(bfsum(aoB) + inoB);
            cA = fmaf(FA, cA, IA * GA);
            cB = fmaf(FB, cB, IB * GB);
            hA = OA * tanha(cA);
            hB = OB * tanha(cB);

            // publish h as bf16
            unsigned short ha16, hb16;
            asm("cvt.rn.bf16.f32 %0, %1;" : "=h"(ha16) : "f"(hA));
            asm("cvt.rn.bf16.f32 %0, %1;" : "=h"(hb16) : "f"(hB));
            hbA[p ^ 1][lane] = ha16;
            hbB[p ^ 1][lane] = hb16;
            __syncwarp();
        }
    }

    // decoder input projection for both rows: pg = sum_j dWih[g][j]*h[j]
    float pA0 = hA * dWih[lane];
    float pA1 = hA * dWih[32 + lane];
    float pA2 = hA * dWih[64 + lane];
    float pA3 = hA * dWih[96 + lane];
    float pB0 = hB * dWih[lane];
    float pB1 = hB * dWih[32 + lane];
    float pB2 = hB * dWih[64 + lane];
    float pB3 = hB * dWih[96 + lane];
    #pragma unroll
    for (int m = 16; m > 0; m >>= 1) {
        pA0 += __shfl_xor_sync(0xffffffffu, pA0, m);
        pA1 += __shfl_xor_sync(0xffffffffu, pA1, m);
        pA2 += __shfl_xor_sync(0xffffffffu, pA2, m);
        pA3 += __shfl_xor_sync(0xffffffffu, pA3, m);
        pB0 += __shfl_xor_sync(0xffffffffu, pB0, m);
        pB1 += __shfl_xor_sync(0xffffffffu, pB1, m);
        pB2 += __shfl_xor_sync(0xffffffffu, pB2, m);
        pB3 += __shfl_xor_sync(0xffffffffu, pB3, m);
    }
    if (lane == 0) {
        g_pre[0][rA] = pA0 + dBih[0] + dBhh[0];
        g_pre[1][rA] = pA1 + dBih[1] + dBhh[1];
        g_pre[2][rA] = pA2 + dBih[2] + dBhh[2];
        g_pre[3][rA] = pA3 + dBih[3] + dBhh[3];
        g_pre[0][rB] = pB0 + dBih[0] + dBhh[0];
        g_pre[1][rB] = pB1 + dBih[1] + dBhh[1];
        g_pre[2][rB] = pB2 + dBih[2] + dBhh[2];
        g_pre[3][rB] = pB3 + dBih[3] + dBhh[3];
    }
}

// ============================================================================
// Decoder: one batch row per THREAD (H=1 scalar recurrence). 8192 threads.
// ============================================================================
__global__ void __launch_bounds__(32) dec_kernel(
    const float* __restrict__ dWhh,   // [4]
    float* __restrict__ out)          // [B, T]
{
    const int r = blockIdx.x * 32 + threadIdx.x;

    const float pre0 = 0.5f * g_pre[0][r];
    const float pre1 = 0.5f * g_pre[1][r];
    const float pre2 =        g_pre[2][r];
    const float pre3 = 0.5f * g_pre[3][r];
    const float q0 = 0.5f * dWhh[0];
    const float q1 = 0.5f * dWhh[1];
    const float q2 =        dWhh[2];
    const float q3 = 0.5f * dWhh[3];

    float hd = 0.0f, cd = 0.0f;
    float* orow = out + (size_t)r * SEQT;

    #pragma unroll 1
    for (int t = 0; t < SEQT; t += 4) {
        float v[4];
        #pragma unroll
        for (int s = 0; s < 4; ++s) {
            const float I = sigm_pre(fmaf(hd, q0, pre0));
            const float F = sigm_pre(fmaf(hd, q1, pre1));
            const float G = tanha(fmaf(hd, q2, pre2));
            const float O = sigm_pre(fmaf(hd, q3, pre3));
            cd = fmaf(F, cd, I * G);
            hd = O * tanha(cd);
            v[s] = hd;
        }
        *(float4*)(orow + t) = make_float4(v[0], v[1], v[2], v[3]);
    }
}

extern "C" void kernel_launch(void* const* d_in, const int* in_sizes, int n_in,
                              void* d_out, int out_size) {
    (void)in_sizes; (void)n_in; (void)out_size;
    enc_kernel<<<BATCH / 2, 32>>>(
        (const float*)d_in[0],
        (const float*)d_in[1], (const float*)d_in[2],
        (const float*)d_in[3], (const float*)d_in[4],
        (const float*)d_in[5],
        (const float*)d_in[7], (const float*)d_in[8]);
    dec_kernel<<<BATCH / 32, 32>>>(
        (const float*)d_in[6],
        (float*)d_out);
}

// round 16
// speedup vs baseline: 1.0281x; 1.0065x over previous
#include <cuda_runtime.h>
#include <cstdint>

typedef unsigned long long ull;

#define BATCH 8192
#define SEQT  256
#define HID   32

// scratch: decoder per-row gate preactivations, transposed for coalesced loads
__device__ float g_pre[4][BATCH];

// ---- f32x2 helpers ----
__device__ __forceinline__ void unpackf2(ull v, float &a, float &b) {
    unsigned lo, hi;
    asm("mov.b64 {%0, %1}, %2;" : "=r"(lo), "=r"(hi) : "l"(v));
    a = __uint_as_float(lo); b = __uint_as_float(hi);
}

// ---- bf16x2 helpers ----
__device__ __forceinline__ void hfma2(unsigned &acc, unsigned a, unsigned b) {
    asm("fma.rn.bf16x2 %0, %1, %2, %0;" : "+r"(acc) : "r"(a), "r"(b));
}
__device__ __forceinline__ unsigned bfpack(float hi, float lo) {
    unsigned r;
    asm("cvt.rn.bf16x2.f32 %0, %1, %2;" : "=r"(r) : "f"(hi), "f"(lo));
    return r;
}
// horizontal sum of a bf16x2 accumulator in f32 (bf16->f32 is an exact shift)
__device__ __forceinline__ float bfsum(unsigned v) {
    return __uint_as_float(v << 16) + __uint_as_float(v & 0xffff0000u);
}

// ---- activations: all MUFU.TANH (calibrated error transfer) ----
__device__ __forceinline__ float tanha(float x) {
    float y;
    asm("tanh.approx.f32 %0, %1;" : "=f"(y) : "f"(x));
    return y;
}
__device__ __forceinline__ float sigm_pre(float acc_half_x) {   // sig(2x) of acc
    return fmaf(0.5f, tanha(acc_half_x), 0.5f);
}

// ============================================================================
// Encoder: ONE WARP per CTA, TWO rows per warp (flat registers — the proven
// fixed point). All recurrent weights in bf16x2 (i/f/o pre-scaled by 0.5 for
// the sigmoid fold; g accumulated in two bf16x2 registers, summed exactly in
// f32). x-term + bias exact f32, computed AFTER the GEMV (short live range)
// and added to the dot in the tail. Single bf16 h ping-pong buffer.
// 17 warps/SM target (reg cap 120).
// ============================================================================
__global__ void __launch_bounds__(32, 17) enc_kernel(
    const float* __restrict__ x,      // [B, T]
    const float* __restrict__ eWih,   // [128]
    const float* __restrict__ eWhh,   // [128, 32]
    const float* __restrict__ eBih,   // [128]
    const float* __restrict__ eBhh,   // [128]
    const float* __restrict__ dWih,   // [4, 32]
    const float* __restrict__ dBih,   // [4]
    const float* __restrict__ dBhh)   // [4]
{
    __shared__ float xsA[SEQT], xsB[SEQT];
    __shared__ __align__(16) unsigned short hbA[2][HID], hbB[2][HID];  // bf16 h

    const int lane = threadIdx.x;
    const int rA   = blockIdx.x * 2;
    const int rB   = rA + 1;

    // stage both x rows (float4-coalesced)
    {
        const float4* a4 = (const float4*)(x + (size_t)rA * SEQT);
        const float4* b4 = (const float4*)(x + (size_t)rB * SEQT);
        ((float4*)xsA)[lane]      = a4[lane];
        ((float4*)xsA)[32 + lane] = a4[32 + lane];
        ((float4*)xsB)[lane]      = b4[lane];
        ((float4*)xsB)[32 + lane] = b4[32 + lane];
    }

    // ---- per-lane weights, all bf16x2 over k-pairs ----
    unsigned wI[16], wF[16], wG[16], wO[16];
    {
        const ull* ri = (const ull*)(eWhh + (size_t)(      lane) * HID);
        const ull* rf = (const ull*)(eWhh + (size_t)(32  + lane) * HID);
        const ull* rg = (const ull*)(eWhh + (size_t)(64  + lane) * HID);
        const ull* ro = (const ull*)(eWhh + (size_t)(96  + lane) * HID);
        #pragma unroll
        for (int k = 0; k < 16; ++k) {
            float lo, hi;
            unpackf2(ri[k], lo, hi);  wI[k] = bfpack(0.5f * hi, 0.5f * lo);
            unpackf2(rf[k], lo, hi);  wF[k] = bfpack(0.5f * hi, 0.5f * lo);
            unpackf2(rg[k], lo, hi);  wG[k] = bfpack(hi, lo);
            unpackf2(ro[k], lo, hi);  wO[k] = bfpack(0.5f * hi, 0.5f * lo);
        }
    }
    const float bi = 0.5f * (eBih[lane]      + eBhh[lane]);
    const float bf = 0.5f * (eBih[32 + lane] + eBhh[32 + lane]);
    const float bg =        (eBih[64 + lane] + eBhh[64 + lane]);
    const float bo = 0.5f * (eBih[96 + lane] + eBhh[96 + lane]);
    const float vi = 0.5f * eWih[lane];
    const float vf = 0.5f * eWih[32 + lane];
    const float vg =        eWih[64 + lane];
    const float vo = 0.5f * eWih[96 + lane];

    hbA[0][lane] = 0;     // bf16 +0.0
    hbB[0][lane] = 0;
    __syncwarp();

    float hA = 0.0f, cA = 0.0f;
    float hB = 0.0f, cB = 0.0f;

    #pragma unroll 1
    for (int t = 0; t < SEQT; t += 2) {
        #pragma unroll
        for (int p = 0; p < 2; ++p) {
            const uint4* bhA = (const uint4*)hbA[p];
            const uint4* bhB = (const uint4*)hbB[p];

            // bf16x2 accumulators; g split over two to halve rounding walk
            unsigned aiA = 0, afA = 0, aoA = 0, ag0A = 0, ag1A = 0;
            unsigned aiB = 0, afB = 0, aoB = 0, ag0B = 0, ag1B = 0;

            #pragma unroll
            for (int q = 0; q < 4; ++q) {
                const uint4 ha = bhA[q];         // LDS.128: 8 bf16 h values
                const uint4 hb = bhB[q];
                hfma2(aiA,  wI[4 * q + 0], ha.x);  hfma2(aiB,  wI[4 * q + 0], hb.x);
                hfma2(afA,  wF[4 * q + 0], ha.x);  hfma2(afB,  wF[4 * q + 0], hb.x);
                hfma2(ag0A, wG[4 * q + 0], ha.x);  hfma2(ag0B, wG[4 * q + 0], hb.x);
                hfma2(aoA,  wO[4 * q + 0], ha.x);  hfma2(aoB,  wO[4 * q + 0], hb.x);
                hfma2(aiA,  wI[4 * q + 1], ha.y);  hfma2(aiB,  wI[4 * q + 1], hb.y);
                hfma2(afA,  wF[4 * q + 1], ha.y);  hfma2(afB,  wF[4 * q + 1], hb.y);
                hfma2(ag1A, wG[4 * q + 1], ha.y);  hfma2(ag1B, wG[4 * q + 1], hb.y);
                hfma2(aoA,  wO[4 * q + 1], ha.y);  hfma2(aoB,  wO[4 * q + 1], hb.y);
                hfma2(aiA,  wI[4 * q + 2], ha.z);  hfma2(aiB,  wI[4 * q + 2], hb.z);
                hfma2(afA,  wF[4 * q + 2], ha.z);  hfma2(afB,  wF[4 * q + 2], hb.z);
                hfma2(ag0A, wG[4 * q + 2], ha.z);  hfma2(ag0B, wG[4 * q + 2], hb.z);
                hfma2(aoA,  wO[4 * q + 2], ha.z);  hfma2(aoB,  wO[4 * q + 2], hb.z);
                hfma2(aiA,  wI[4 * q + 3], ha.w);  hfma2(aiB,  wI[4 * q + 3], hb.w);
                hfma2(afA,  wF[4 * q + 3], ha.w);  hfma2(afB,  wF[4 * q + 3], hb.w);
                hfma2(ag1A, wG[4 * q + 3], ha.w);  hfma2(ag1B, wG[4 * q + 3], hb.w);
                hfma2(aoA,  wO[4 * q + 3], ha.w);  hfma2(aoB,  wO[4 * q + 3], hb.w);
            }

            // f32 init terms computed HERE (short live range; exact math,
            // same values as before — adds after the dot, unchanged results)
            const float xa = xsA[t + p];
            const float xb = xsB[t + p];
            const float iniA = fmaf(xa, vi, bi), infA = fmaf(xa, vf, bf);
            const float ingA = fmaf(xa, vg, bg), inoA = fmaf(xa, vo, bo);
            const float iniB = fmaf(xb, vi, bi), infB = fmaf(xb, vf, bf);
            const float ingB = fmaf(xb, vg, bg), inoB = fmaf(xb, vo, bo);

            // ---- activations + state update (all MUFU.TANH) ----
            const float IA = sigm_pre(bfsum(aiA) + iniA);
            const float IB = sigm_pre(bfsum(aiB) + iniB);
            const float FA = sigm_pre(bfsum(afA) + infA);
            const float FB = sigm_pre(bfsum(afB) + infB);
            const float GA = tanha((bfsum(ag0A) + bfsum(ag1A)) + ingA);
            const float GB = tanha((bfsum(ag0B) + bfsum(ag1B)) + ingB);
            const float OA = sigm_pre(bfsum(aoA) + inoA);
            const float OB = sigm_pre(bfsum(aoB) + inoB);
            cA = fmaf(FA, cA, IA * GA);
            cB = fmaf(FB, cB, IB * GB);
            hA = OA * tanha(cA);
            hB = OB * tanha(cB);

            // publish h as bf16
            unsigned short ha16, hb16;
            asm("cvt.rn.bf16.f32 %0, %1;" : "=h"(ha16) : "f"(hA));
            asm("cvt.rn.bf16.f32 %0, %1;" : "=h"(hb16) : "f"(hB));
            hbA[p ^ 1][lane] = ha16;
            hbB[p ^ 1][lane] = hb16;
            __syncwarp();
        }
    }

    // decoder input projection for both rows: pg = sum_j dWih[g][j]*h[j]
    float pA0 = hA * dWih[lane];
    float pA1 = hA * dWih[32 + lane];
    float pA2 = hA * dWih[64 + lane];
    float pA3 = hA * dWih[96 + lane];
    float pB0 = hB * dWih[lane];
    float pB1 = hB * dWih[32 + lane];
    float pB2 = hB * dWih[64 + lane];
    float pB3 = hB * dWih[96 + lane];
    #pragma unroll
    for (int m = 16; m > 0; m >>= 1) {
        pA0 += __shfl_xor_sync(0xffffffffu, pA0, m);
        pA1 += __shfl_xor_sync(0xffffffffu, pA1, m);
        pA2 += __shfl_xor_sync(0xffffffffu, pA2, m);
        pA3 += __shfl_xor_sync(0xffffffffu, pA3, m);
        pB0 += __shfl_xor_sync(0xffffffffu, pB0, m);
        pB1 += __shfl_xor_sync(0xffffffffu, pB1, m);
        pB2 += __shfl_xor_sync(0xffffffffu, pB2, m);
        pB3 += __shfl_xor_sync(0xffffffffu, pB3, m);
    }
    if (lane == 0) {
        g_pre[0][rA] = pA0 + dBih[0] + dBhh[0];
        g_pre[1][rA] = pA1 + dBih[1] + dBhh[1];
        g_pre[2][rA] = pA2 + dBih[2] + dBhh[2];
        g_pre[3][rA] = pA3 + dBih[3] + dBhh[3];
        g_pre[0][rB] = pB0 + dBih[0] + dBhh[0];
        g_pre[1][rB] = pB1 + dBih[1] + dBhh[1];
        g_pre[2][rB] = pB2 + dBih[2] + dBhh[2];
        g_pre[3][rB] = pB3 + dBih[3] + dBhh[3];
    }
}

// ============================================================================
// Decoder: one batch row per THREAD (H=1 scalar recurrence). 8192 threads.
// ============================================================================
__global__ void __launch_bounds__(32) dec_kernel(
    const float* __restrict__ dWhh,   // [4]
    float* __restrict__ out)          // [B, T]
{
    const int r = blockIdx.x * 32 + threadIdx.x;

    const float pre0 = 0.5f * g_pre[0][r];
    const float pre1 = 0.5f * g_pre[1][r];
    const float pre2 =        g_pre[2][r];
    const float pre3 = 0.5f * g_pre[3][r];
    const float q0 = 0.5f * dWhh[0];
    const float q1 = 0.5f * dWhh[1];
    const float q2 =        dWhh[2];
    const float q3 = 0.5f * dWhh[3];

    float hd = 0.0f, cd = 0.0f;
    float* orow = out + (size_t)r * SEQT;

    #pragma unroll 1
    for (int t = 0; t < SEQT; t += 4) {
        float v[4];
        #pragma unroll
        for (int s = 0; s < 4; ++s) {
            const float I = sigm_pre(fmaf(hd, q0, pre0));
            const float F = sigm_pre(fmaf(hd, q1, pre1));
            const float G = tanha(fmaf(hd, q2, pre2));
            const float O = sigm_pre(fmaf(hd, q3, pre3));
            cd = fmaf(F, cd, I * G);
            hd = O * tanha(cd);
            v[s] = hd;
        }
        *(float4*)(orow + t) = make_float4(v[0], v[1], v[2], v[3]);
    }
}

extern "C" void kernel_launch(void* const* d_in, const int* in_sizes, int n_in,
                              void* d_out, int out_size) {
    (void)in_sizes; (void)n_in; (void)out_size;
    enc_kernel<<<BATCH / 2, 32>>>(
        (const float*)d_in[0],
        (const float*)d_in[1], (const float*)d_in[2],
        (const float*)d_in[3], (const float*)d_in[4],
        (const float*)d_in[5],
        (const float*)d_in[7], (const float*)d_in[8]);
    dec_kernel<<<BATCH / 32, 32>>>(
        (const float*)d_in[6],
        (float*)d_out);
}

// round 17
// speedup vs baseline: 1.0286x; 1.0005x over previous
#include <cuda_runtime.h>
#include <cstdint>

typedef unsigned long long ull;

#define BATCH 8192
#define SEQT  256
#define HID   32

// scratch: decoder per-row gate preactivations, transposed for coalesced loads
__device__ float g_pre[4][BATCH];

// ---- f32x2 helpers ----
__device__ __forceinline__ void unpackf2(ull v, float &a, float &b) {
    unsigned lo, hi;
    asm("mov.b64 {%0, %1}, %2;" : "=r"(lo), "=r"(hi) : "l"(v));
    a = __uint_as_float(lo); b = __uint_as_float(hi);
}

// ---- bf16x2 helpers ----
__device__ __forceinline__ void hfma2(unsigned &acc, unsigned a, unsigned b) {
    asm("fma.rn.bf16x2 %0, %1, %2, %0;" : "+r"(acc) : "r"(a), "r"(b));
}
__device__ __forceinline__ unsigned bfpack(float hi, float lo) {
    unsigned r;
    asm("cvt.rn.bf16x2.f32 %0, %1, %2;" : "=r"(r) : "f"(hi), "f"(lo));
    return r;
}
// horizontal sum of a bf16x2 accumulator in f32 (bf16->f32 is an exact shift)
__device__ __forceinline__ float bfsum(unsigned v) {
    return __uint_as_float(v << 16) + __uint_as_float(v & 0xffff0000u);
}

// ---- activations: all MUFU.TANH (calibrated error transfer) ----
__device__ __forceinline__ float tanha(float x) {
    float y;
    asm("tanh.approx.f32 %0, %1;" : "=f"(y) : "f"(x));
    return y;
}
__device__ __forceinline__ float sigm_pre(float acc_half_x) {   // sig(2x) of acc
    return fmaf(0.5f, tanha(acc_half_x), 0.5f);
}

// ============================================================================
// Encoder: ONE WARP per CTA, TWO rows per warp (flat registers — the proven
// fixed point). All recurrent weights in bf16x2 (i/f/o pre-scaled by 0.5 for
// the sigmoid fold; g accumulated in two bf16x2 registers, summed exactly in
// f32). x-term + bias exact f32, computed AFTER the GEMV (short live range)
// and added to the dot in the tail. Single bf16 h ping-pong buffer.
// 17 warps/SM target (reg cap 120).
// ============================================================================
__global__ void __launch_bounds__(32, 17) enc_kernel(
    const float* __restrict__ x,      // [B, T]
    const float* __restrict__ eWih,   // [128]
    const float* __restrict__ eWhh,   // [128, 32]
    const float* __restrict__ eBih,   // [128]
    const float* __restrict__ eBhh,   // [128]
    const float* __restrict__ dWih,   // [4, 32]
    const float* __restrict__ dBih,   // [4]
    const float* __restrict__ dBhh)   // [4]
{
    __shared__ float xsA[SEQT], xsB[SEQT];
    __shared__ __align__(16) unsigned short hbA[2][HID], hbB[2][HID];  // bf16 h

    const int lane = threadIdx.x;
    const int rA   = blockIdx.x * 2;
    const int rB   = rA + 1;

    // stage both x rows (float4-coalesced)
    {
        const float4* a4 = (const float4*)(x + (size_t)rA * SEQT);
        const float4* b4 = (const float4*)(x + (size_t)rB * SEQT);
        ((float4*)xsA)[lane]      = a4[lane];
        ((float4*)xsA)[32 + lane] = a4[32 + lane];
        ((float4*)xsB)[lane]      = b4[lane];
        ((float4*)xsB)[32 + lane] = b4[32 + lane];
    }

    // ---- per-lane weights, all bf16x2 over k-pairs ----
    unsigned wI[16], wF[16], wG[16], wO[16];
    {
        const ull* ri = (const ull*)(eWhh + (size_t)(      lane) * HID);
        const ull* rf = (const ull*)(eWhh + (size_t)(32  + lane) * HID);
        const ull* rg = (const ull*)(eWhh + (size_t)(64  + lane) * HID);
        const ull* ro = (const ull*)(eWhh + (size_t)(96  + lane) * HID);
        #pragma unroll
        for (int k = 0; k < 16; ++k) {
            float lo, hi;
            unpackf2(ri[k], lo, hi);  wI[k] = bfpack(0.5f * hi, 0.5f * lo);
            unpackf2(rf[k], lo, hi);  wF[k] = bfpack(0.5f * hi, 0.5f * lo);
            unpackf2(rg[k], lo, hi);  wG[k] = bfpack(hi, lo);
            unpackf2(ro[k], lo, hi);  wO[k] = bfpack(0.5f * hi, 0.5f * lo);
        }
    }
    const float bi = 0.5f * (eBih[lane]      + eBhh[lane]);
    const float bf = 0.5f * (eBih[32 + lane] + eBhh[32 + lane]);
    const float bg =        (eBih[64 + lane] + eBhh[64 + lane]);
    const float bo = 0.5f * (eBih[96 + lane] + eBhh[96 + lane]);
    const float vi = 0.5f * eWih[lane];
    const float vf = 0.5f * eWih[32 + lane];
    const float vg =        eWih[64 + lane];
    const float vo = 0.5f * eWih[96 + lane];

    hbA[0][lane] = 0;     // bf16 +0.0
    hbB[0][lane] = 0;
    __syncwarp();

    float hA = 0.0f, cA = 0.0f;
    float hB = 0.0f, cB = 0.0f;

    #pragma unroll 1
    for (int t = 0; t < SEQT; t += 2) {
        #pragma unroll
        for (int p = 0; p < 2; ++p) {
            const uint4* bhA = (const uint4*)hbA[p];
            const uint4* bhB = (const uint4*)hbB[p];

            // bf16x2 accumulators; g split over two to halve rounding walk
            unsigned aiA = 0, afA = 0, aoA = 0, ag0A = 0, ag1A = 0;
            unsigned aiB = 0, afB = 0, aoB = 0, ag0B = 0, ag1B = 0;

            #pragma unroll
            for (int q = 0; q < 4; ++q) {
                const uint4 ha = bhA[q];         // LDS.128: 8 bf16 h values
                const uint4 hb = bhB[q];
                hfma2(aiA,  wI[4 * q + 0], ha.x);  hfma2(aiB,  wI[4 * q + 0], hb.x);
                hfma2(afA,  wF[4 * q + 0], ha.x);  hfma2(afB,  wF[4 * q + 0], hb.x);
                hfma2(ag0A, wG[4 * q + 0], ha.x);  hfma2(ag0B, wG[4 * q + 0], hb.x);
                hfma2(aoA,  wO[4 * q + 0], ha.x);  hfma2(aoB,  wO[4 * q + 0], hb.x);
                hfma2(aiA,  wI[4 * q + 1], ha.y);  hfma2(aiB,  wI[4 * q + 1], hb.y);
                hfma2(afA,  wF[4 * q + 1], ha.y);  hfma2(afB,  wF[4 * q + 1], hb.y);
                hfma2(ag1A, wG[4 * q + 1], ha.y);  hfma2(ag1B, wG[4 * q + 1], hb.y);
                hfma2(aoA,  wO[4 * q + 1], ha.y);  hfma2(aoB,  wO[4 * q + 1], hb.y);
                hfma2(aiA,  wI[4 * q + 2], ha.z);  hfma2(aiB,  wI[4 * q + 2], hb.z);
                hfma2(afA,  wF[4 * q + 2], ha.z);  hfma2(afB,  wF[4 * q + 2], hb.z);
                hfma2(ag0A, wG[4 * q + 2], ha.z);  hfma2(ag0B, wG[4 * q + 2], hb.z);
                hfma2(aoA,  wO[4 * q + 2], ha.z);  hfma2(aoB,  wO[4 * q + 2], hb.z);
                hfma2(aiA,  wI[4 * q + 3], ha.w);  hfma2(aiB,  wI[4 * q + 3], hb.w);
                hfma2(afA,  wF[4 * q + 3], ha.w);  hfma2(afB,  wF[4 * q + 3], hb.w);
                hfma2(ag1A, wG[4 * q + 3], ha.w);  hfma2(ag1B, wG[4 * q + 3], hb.w);
                hfma2(aoA,  wO[4 * q + 3], ha.w);  hfma2(aoB,  wO[4 * q + 3], hb.w);
            }

            // f32 init terms computed HERE (short live range; exact math,
            // same values as before — adds after the dot, unchanged results)
            const float xa = xsA[t + p];
            const float xb = xsB[t + p];
            const float iniA = fmaf(xa, vi, bi), infA = fmaf(xa, vf, bf);
            const float ingA = fmaf(xa, vg, bg), inoA = fmaf(xa, vo, bo);
            const float iniB = fmaf(xb, vi, bi), infB = fmaf(xb, vf, bf);
            const float ingB = fmaf(xb, vg, bg), inoB = fmaf(xb, vo, bo);

            // ---- activations + state update (all MUFU.TANH) ----
            const float IA = sigm_pre(bfsum(aiA) + iniA);
            const float IB = sigm_pre(bfsum(aiB) + iniB);
            const float FA = sigm_pre(bfsum(afA) + infA);
            const float FB = sigm_pre(bfsum(afB) + infB);
            const float GA = tanha((bfsum(ag0A) + bfsum(ag1A)) + ingA);
            const float GB = tanha((bfsum(ag0B) + bfsum(ag1B)) + ingB);
            const float OA = sigm_pre(bfsum(aoA) + inoA);
            const float OB = sigm_pre(bfsum(aoB) + inoB);
            cA = fmaf(FA, cA, IA * GA);
            cB = fmaf(FB, cB, IB * GB);
            hA = OA * tanha(cA);
            hB = OB * tanha(cB);

            // publish h as bf16
            unsigned short ha16, hb16;
            asm("cvt.rn.bf16.f32 %0, %1;" : "=h"(ha16) : "f"(hA));
            asm("cvt.rn.bf16.f32 %0, %1;" : "=h"(hb16) : "f"(hB));
            hbA[p ^ 1][lane] = ha16;
            hbB[p ^ 1][lane] = hb16;
            __syncwarp();
        }
    }

    // decoder input projection for both rows: pg = sum_j dWih[g][j]*h[j]
    float pA0 = hA * dWih[lane];
    float pA1 = hA * dWih[32 + lane];
    float pA2 = hA * dWih[64 + lane];
    float pA3 = hA * dWih[96 + lane];
    float pB0 = hB * dWih[lane];
    float pB1 = hB * dWih[32 + lane];
    float pB2 = hB * dWih[64 + lane];
    float pB3 = hB * dWih[96 + lane];
    #pragma unroll
    for (int m = 16; m > 0; m >>= 1) {
        pA0 += __shfl_xor_sync(0xffffffffu, pA0, m);
        pA1 += __shfl_xor_sync(0xffffffffu, pA1, m);
        pA2 += __shfl_xor_sync(0xffffffffu, pA2, m);
        pA3 += __shfl_xor_sync(0xffffffffu, pA3, m);
        pB0 += __shfl_xor_sync(0xffffffffu, pB0, m);
        pB1 += __shfl_xor_sync(0xffffffffu, pB1, m);
        pB2 += __shfl_xor_sync(0xffffffffu, pB2, m);
        pB3 += __shfl_xor_sync(0xffffffffu, pB3, m);
    }
    if (lane == 0) {
        g_pre[0][rA] = pA0 + dBih[0] + dBhh[0];
        g_pre[1][rA] = pA1 + dBih[1] + dBhh[1];
        g_pre[2][rA] = pA2 + dBih[2] + dBhh[2];
        g_pre[3][rA] = pA3 + dBih[3] + dBhh[3];
        g_pre[0][rB] = pB0 + dBih[0] + dBhh[0];
        g_pre[1][rB] = pB1 + dBih[1] + dBhh[1];
        g_pre[2][rB] = pB2 + dBih[2] + dBhh[2];
        g_pre[3][rB] = pB3 + dBih[3] + dBhh[3];
    }
}

// ============================================================================
// Decoder: one batch row per THREAD (H=1 scalar recurrence). 8192 threads.
// ============================================================================
__global__ void __launch_bounds__(32) dec_kernel(
    const float* __restrict__ dWhh,   // [4]
    float* __restrict__ out)          // [B, T]
{
    const int r = blockIdx.x * 32 + threadIdx.x;

    const float pre0 = 0.5f * g_pre[0][r];
    const float pre1 = 0.5f * g_pre[1][r];
    const float pre2 =        g_pre[2][r];
    const float pre3 = 0.5f * g_pre[3][r];
    const float q0 = 0.5f * dWhh[0];
    const float q1 = 0.5f * dWhh[1];
    const float q2 =        dWhh[2];
    const float q3 = 0.5f * dWhh[3];

    float hd = 0.0f, cd = 0.0f;
    float* orow = out + (size_t)r * SEQT;

    #pragma unroll 1
    for (int t = 0; t < SEQT; t += 4) {
        float v[4];
        #pragma unroll
        for (int s = 0; s < 4; ++s) {
            const float I = sigm_pre(fmaf(hd, q0, pre0));
            const float F = sigm_pre(fmaf(hd, q1, pre1));
            const float G = tanha(fmaf(hd, q2, pre2));
            const float O = sigm_pre(fmaf(hd, q3, pre3));
            cd = fmaf(F, cd, I * G);
            hd = O * tanha(cd);
            v[s] = hd;
        }
        *(float4*)(orow + t) = make_float4(v[0], v[1], v[2], v[3]);
    }
}

extern "C" void kernel_launch(void* const* d_in, const int* in_sizes, int n_in,
                              void* d_out, int out_size) {
    (void)in_sizes; (void)n_in; (void)out_size;
    enc_kernel<<<BATCH / 2, 32>>>(
        (const float*)d_in[0],
        (const float*)d_in[1], (const float*)d_in[2],
        (const float*)d_in[3], (const float*)d_in[4],
        (const float*)d_in[5],
        (const float*)d_in[7], (const float*)d_in[8]);
    dec_kernel<<<BATCH / 32, 32>>>(
        (const float*)d_in[6],
        (float*)d_out);
}